// round 11
// baseline (speedup 1.0000x reference)
#include <cuda_runtime.h>
#include <cstdint>
#include <cstddef>

#define S_LEN 4096
#define D_DIM 2048
#define V_DIM 64000
#define NBINS (1 << 20)     // bin = key >> 12
#define NGROUPS 1024        // 1024 bins per group
#define BIN_SMEM 2048
#define NSEG 16             // split-K segments for the big GEMV
#define POOL_CH 128         // j-chunks for pooling (32 each)

// ---------------- static scratch (no allocations allowed) ----------------
__device__ float  g_s[S_LEN];
__device__ float  g_scores[S_LEN];
__device__ double g_pool_part[POOL_CH][D_DIM];
__device__ float  g_pooled[D_DIM];
__device__ double g_logit_part[NSEG][V_DIM];
__device__ float  g_logits[V_DIM];
__device__ float  g_maxl;
__device__ float  g_e[V_DIM];
__device__ double g_zpart[256];
__device__ float  g_Z;
__device__ unsigned g_key[V_DIM];
__device__ unsigned g_hist[NBINS];
__device__ unsigned g_base[NBINS];
__device__ unsigned g_fill[NBINS];
__device__ unsigned g_groupsum[NGROUPS];
__device__ unsigned g_groupbase[NGROUPS];
__device__ int      g_nbins;
__device__ int      g_binlist[NBINS];
__device__ unsigned g_slotkey[V_DIM];
__device__ int      g_slotidx[V_DIM];
__device__ float    g_sortp[V_DIM];
__device__ int      g_order[V_DIM];
__device__ unsigned char g_mask[V_DIM];
__device__ unsigned long long g_best;

// ---------------- threefry2x32 (bit-exact JAX PRNG) ----------------
__device__ __forceinline__ uint32_t rotl32(uint32_t v, int n) {
    return (v << n) | (v >> (32 - n));
}

__device__ __forceinline__ void threefry2x32(uint32_t k0, uint32_t k1,
                                             uint32_t& x0, uint32_t& x1) {
    uint32_t ks[3] = {k0, k1, k0 ^ k1 ^ 0x1BD11BDAu};
    const int rotA[4] = {13, 15, 26, 6};
    const int rotB[4] = {17, 29, 16, 24};
    x0 += ks[0]; x1 += ks[1];
#pragma unroll
    for (int i = 0; i < 5; i++) {
        const int* r = (i & 1) ? rotB : rotA;
#pragma unroll
        for (int k = 0; k < 4; k++) {
            x0 += x1;
            x1 = rotl32(x1, r[k]);
            x1 ^= x0;
        }
        x0 += ks[(i + 1) % 3];
        x1 += ks[(i + 2) % 3] + (uint32_t)(i + 1);
    }
}

// ---------------- kernels ----------------
__global__ void k_reset() {
    if (threadIdx.x == 0) { g_best = 0ull; g_nbins = 0; }
}

// s[j] = batch[j,:] . pool_w  (float4 loads, per-product fp64 accumulate)
__global__ void k_scoredot(const float* __restrict__ batch,
                           const float* __restrict__ pw) {
    int j = blockIdx.x;
    int t = threadIdx.x;  // 256
    const float4* row4 = reinterpret_cast<const float4*>(batch + (size_t)j * D_DIM);
    const float4* pw4  = reinterpret_cast<const float4*>(pw);
    double acc = 0.0;
#pragma unroll
    for (int k = 0; k < 2; k++) {
        int i = t + k * 256;          // 512 float4 = 2048 floats
        float4 a = row4[i];
        float4 b = pw4[i];
        acc += (double)(a.x * b.x);
        acc += (double)(a.y * b.y);
        acc += (double)(a.z * b.z);
        acc += (double)(a.w * b.w);
    }
    __shared__ double sm[256];
    sm[t] = acc;
    __syncthreads();
    for (int o = 128; o > 0; o >>= 1) {
        if (t < o) sm[t] += sm[t + o];
        __syncthreads();
    }
    if (t == 0) g_s[j] = (float)sm[0];
}

// softmax over S (single block)
__global__ void k_softmax_scores() {
    __shared__ float smx[1024];
    __shared__ double smd[1024];
    int t = threadIdx.x;
    float m = -3.4e38f;
    for (int i = t; i < S_LEN; i += 1024) m = fmaxf(m, g_s[i]);
    smx[t] = m;
    __syncthreads();
    for (int o = 512; o > 0; o >>= 1) {
        if (t < o) smx[t] = fmaxf(smx[t], smx[t + o]);
        __syncthreads();
    }
    float gm = smx[0];
    __syncthreads();
    double sum = 0.0;
    for (int i = t; i < S_LEN; i += 1024) {
        float e = expf(g_s[i] - gm);
        g_scores[i] = e;
        sum += (double)e;
    }
    smd[t] = sum;
    __syncthreads();
    for (int o = 512; o > 0; o >>= 1) {
        if (t < o) smd[t] += smd[t + o];
        __syncthreads();
    }
    float Z = (float)smd[0];
    __syncthreads();
    for (int i = t; i < S_LEN; i += 1024) g_scores[i] = g_scores[i] / Z;
}

// pooled partials: 32 j per block, float4 across d (4 d-lanes per thread),
// per-lane fp32 chunk-of-8 + fp64 fold (identical per-d numerics to prior pass)
__global__ void k_pool_part(const float* __restrict__ batch) {
    int d4 = blockIdx.x * 128 + threadIdx.x;  // grid.x = 4 -> 512 float4 lanes
    int c = blockIdx.y;                        // 0..127
    int j0 = c * 32;
    const float4* b4 = reinterpret_cast<const float4*>(batch);
    double a0 = 0.0, a1 = 0.0, a2 = 0.0, a3 = 0.0;
#pragma unroll
    for (int jj = 0; jj < 32; jj += 8) {
        float c0 = 0.f, c1 = 0.f, c2 = 0.f, c3 = 0.f;
#pragma unroll
        for (int k = 0; k < 8; k++) {
            int j = j0 + jj + k;
            float s = g_scores[j];
            float4 b = b4[(size_t)j * (D_DIM / 4) + d4];
            c0 = fmaf(s, b.x, c0);
            c1 = fmaf(s, b.y, c1);
            c2 = fmaf(s, b.z, c2);
            c3 = fmaf(s, b.w, c3);
        }
        a0 += (double)c0;
        a1 += (double)c1;
        a2 += (double)c2;
        a3 += (double)c3;
    }
    int d = d4 * 4;
    g_pool_part[c][d + 0] = a0;
    g_pool_part[c][d + 1] = a1;
    g_pool_part[c][d + 2] = a2;
    g_pool_part[c][d + 3] = a3;
}

// 8 interleaved fp64 accumulators: break the 47-cycle DADD chain
__global__ void k_pool_reduce() {
    int d = blockIdx.x * 256 + threadIdx.x;  // grid 8
    double a[8] = {0, 0, 0, 0, 0, 0, 0, 0};
#pragma unroll
    for (int c = 0; c < POOL_CH; c += 8) {
#pragma unroll
        for (int k = 0; k < 8; k++) a[k] += g_pool_part[c + k][d];
    }
    double s = ((a[0] + a[1]) + (a[2] + a[3])) + ((a[4] + a[5]) + (a[6] + a[7]));
    g_pooled[d] = (float)s;
}

// big GEMV, float4 across v: each thread owns 4 consecutive outputs.
// Per-lane numerics identical to prior passing kernel (chunk-of-16, 4 chains, fp64 fold).
__global__ void __launch_bounds__(128) k_logits_part(const float* __restrict__ W) {
    int v4 = blockIdx.x * 128 + threadIdx.x;  // grid.x = 125 -> 16000 float4 lanes
    int seg = blockIdx.y;                      // 0..15
    int d0 = seg * 128;
    __shared__ float sp[128];
    if (threadIdx.x < 128) sp[threadIdx.x] = g_pooled[d0 + threadIdx.x];
    __syncthreads();
    const float4* wp = reinterpret_cast<const float4*>(W) + (size_t)d0 * (V_DIM / 4) + v4;
    double ax = 0.0, ay = 0.0, az = 0.0, aw = 0.0;
    for (int d = 0; d < 128; d += 16) {
        float4 w[16];
#pragma unroll
        for (int k = 0; k < 16; k++)
            w[k] = wp[(size_t)(d + k) * (V_DIM / 4)];
        float x0 = 0.f, x1 = 0.f, x2 = 0.f, x3 = 0.f;
        float y0 = 0.f, y1 = 0.f, y2 = 0.f, y3 = 0.f;
        float z0 = 0.f, z1 = 0.f, z2 = 0.f, z3 = 0.f;
        float u0 = 0.f, u1 = 0.f, u2 = 0.f, u3 = 0.f;
#pragma unroll
        for (int k = 0; k < 16; k += 4) {
            float p0 = sp[d + k + 0], p1 = sp[d + k + 1];
            float p2 = sp[d + k + 2], p3 = sp[d + k + 3];
            x0 = fmaf(p0, w[k + 0].x, x0); x1 = fmaf(p1, w[k + 1].x, x1);
            x2 = fmaf(p2, w[k + 2].x, x2); x3 = fmaf(p3, w[k + 3].x, x3);
            y0 = fmaf(p0, w[k + 0].y, y0); y1 = fmaf(p1, w[k + 1].y, y1);
            y2 = fmaf(p2, w[k + 2].y, y2); y3 = fmaf(p3, w[k + 3].y, y3);
            z0 = fmaf(p0, w[k + 0].z, z0); z1 = fmaf(p1, w[k + 1].z, z1);
            z2 = fmaf(p2, w[k + 2].z, z2); z3 = fmaf(p3, w[k + 3].z, z3);
            u0 = fmaf(p0, w[k + 0].w, u0); u1 = fmaf(p1, w[k + 1].w, u1);
            u2 = fmaf(p2, w[k + 2].w, u2); u3 = fmaf(p3, w[k + 3].w, u3);
        }
        ax += (double)((x0 + x1) + (x2 + x3));
        ay += (double)((y0 + y1) + (y2 + y3));
        az += (double)((z0 + z1) + (z2 + z3));
        aw += (double)((u0 + u1) + (u2 + u3));
    }
    int v = v4 * 4;
    g_logit_part[seg][v + 0] = ax;
    g_logit_part[seg][v + 1] = ay;
    g_logit_part[seg][v + 2] = az;
    g_logit_part[seg][v + 3] = aw;
}

__global__ void k_logits_final(const float* __restrict__ b) {
    int v = blockIdx.x * 256 + threadIdx.x;  // grid 250
    double s = 0.0;
#pragma unroll
    for (int k = 0; k < NSEG; k++) s += g_logit_part[k][v];
    float m = (float)s;
    m = m + b[v];            // reference adds bias in fp32
    g_logits[v] = 0.7f * m;  // TEMPERATURE
}

__global__ void k_maxl() {
    __shared__ float sm[1024];
    int t = threadIdx.x;
    float m = -3.4e38f;
    for (int i = t; i < V_DIM; i += 1024) m = fmaxf(m, g_logits[i]);
    sm[t] = m;
    __syncthreads();
    for (int o = 512; o > 0; o >>= 1) {
        if (t < o) sm[t] = fmaxf(sm[t], sm[t + o]);
        __syncthreads();
    }
    if (t == 0) g_maxl = sm[0];
}

__global__ void k_exp() {
    int v = blockIdx.x * 256 + threadIdx.x;
    float e = expf(g_logits[v] - g_maxl);
    g_e[v] = e;
    __shared__ double sd[256];
    sd[threadIdx.x] = (double)e;
    __syncthreads();
    for (int o = 128; o > 0; o >>= 1) {
        if (threadIdx.x < o) sd[threadIdx.x] += sd[threadIdx.x + o];
        __syncthreads();
    }
    if (threadIdx.x == 0) g_zpart[blockIdx.x] = sd[0];
}

__global__ void k_zred() {
    __shared__ double sd[256];
    int t = threadIdx.x;
    sd[t] = (t < 250) ? g_zpart[t] : 0.0;
    __syncthreads();
    for (int o = 128; o > 0; o >>= 1) {
        if (t < o) sd[t] += sd[t + o];
        __syncthreads();
    }
    if (t == 0) g_Z = (float)sd[0];
}

__global__ void k_phist() {
    int v = blockIdx.x * 256 + threadIdx.x;
    float p = g_e[v] / g_Z;
    unsigned key = __float_as_uint(p);
    g_key[v] = key;
    atomicAdd(&g_hist[key >> 12], 1u);
}

// scan A: per-group (1024 bins) suffix-exclusive scan + group sums + binlist
__global__ void k_scanA() {
    int g = blockIdx.x;       // 0..1023
    int t = threadIdx.x;      // 1024
    int b = g * 1024 + t;
    unsigned h = g_hist[b];
    __shared__ unsigned s[1024];
    s[t] = h;
    __syncthreads();
    for (int off = 1; off < 1024; off <<= 1) {
        unsigned add = (t >= off) ? s[t - off] : 0u;
        __syncthreads();
        s[t] += add;
        __syncthreads();
    }
    unsigned total = s[1023];
    g_base[b] = total - s[t];
    if (t == 0) g_groupsum[g] = total;
    if (h > 0) {
        int p = atomicAdd(&g_nbins, 1);
        g_binlist[p] = b;
    }
}

// scan B: suffix-exclusive scan across 1024 group sums
__global__ void k_scanB() {
    int t = threadIdx.x;  // 1024
    __shared__ unsigned s[1024];
    s[t] = g_groupsum[t];
    __syncthreads();
    for (int off = 1; off < 1024; off <<= 1) {
        unsigned add = (t >= off) ? s[t - off] : 0u;
        __syncthreads();
        s[t] += add;
        __syncthreads();
    }
    unsigned total = s[1023];
    g_groupbase[t] = total - s[t];
}

__global__ void k_scatter() {
    int v = blockIdx.x * 256 + threadIdx.x;
    unsigned key = g_key[v];
    unsigned b = key >> 12;
    unsigned pos = g_groupbase[b >> 10] + g_base[b] + atomicAdd(&g_fill[b], 1u);
    g_slotkey[pos] = key;
    g_slotidx[pos] = v;
}

// exact rank within bin: descending key, ties by ascending original index
__global__ void k_rank() {
    __shared__ unsigned sk[BIN_SMEM];
    __shared__ int si[BIN_SMEM];
    int nb = g_nbins;
    for (int bi = blockIdx.x; bi < nb; bi += gridDim.x) {
        int b = g_binlist[bi];
        unsigned c = g_hist[b];
        unsigned base = g_groupbase[b >> 10] + g_base[b];
        if (c <= BIN_SMEM) {
            for (unsigned e = threadIdx.x; e < c; e += blockDim.x) {
                sk[e] = g_slotkey[base + e];
                si[e] = g_slotidx[base + e];
            }
            __syncthreads();
            for (unsigned e = threadIdx.x; e < c; e += blockDim.x) {
                unsigned ke = sk[e];
                int ide = si[e];
                unsigned r = 0;
                for (unsigned u = 0; u < c; u++) {
                    unsigned ku = sk[u];
                    r += (ku > ke) || (ku == ke && si[u] < ide);
                }
                g_sortp[base + r] = __uint_as_float(ke);
                g_order[base + r] = ide;
            }
            __syncthreads();
        } else {
            for (unsigned e = threadIdx.x; e < c; e += blockDim.x) {
                unsigned ke = g_slotkey[base + e];
                int ide = g_slotidx[base + e];
                unsigned r = 0;
                for (unsigned u = 0; u < c; u++) {
                    unsigned ku = g_slotkey[base + u];
                    r += (ku > ke) || (ku == ke && g_slotidx[base + u] < ide);
                }
                g_sortp[base + r] = __uint_as_float(ke);
                g_order[base + r] = ide;
            }
            __syncthreads();
        }
    }
}

// inclusive cumsum (fp64) + top-p mask
__global__ void k_cummask() {
    __shared__ double sd[1024];
    int t = threadIdx.x;
    int i0 = t * 64;
    double s = 0.0;
    for (int k = 0; k < 64; k++) {
        int i = i0 + k;
        if (i < V_DIM) s += (double)g_sortp[i];
    }
    sd[t] = s;
    __syncthreads();
    for (int off = 1; off < 1024; off <<= 1) {
        double add = (t >= off) ? sd[t - off] : 0.0;
        __syncthreads();
        sd[t] += add;
        __syncthreads();
    }
    double run = (t > 0) ? sd[t - 1] : 0.0;
    for (int k = 0; k < 64; k++) {
        int i = i0 + k;
        if (i < V_DIM) {
            run += (double)g_sortp[i];
            g_mask[i] = (run <= 0.5) ? 1 : 0;
        }
    }
}

// gumbel-argmax; JAX partitionable threefry, 32-bit draw = y0 ^ y1
__global__ void k_argmax() {
    int i = blockIdx.x * 256 + threadIdx.x;
    if (i >= V_DIM) return;
    if (!g_mask[i]) return;
    uint32_t x0 = 0u, x1 = (uint32_t)i;
    threefry2x32(0u, 42u, x0, x1);
    uint32_t bits = x0 ^ x1;
    float f = __uint_as_float((bits >> 9) | 0x3f800000u) - 1.0f;  // [0,1)
    float u = (f > 0.0f) ? f : 1.17549435e-38f;
    float g = -logf(-logf(u));
    float val = logf(g_sortp[i]) + g;
    uint32_t ob = __float_as_uint(val);
    ob = (ob & 0x80000000u) ? ~ob : (ob | 0x80000000u);
    unsigned long long pk =
        (((unsigned long long)ob) << 32) |
        (unsigned long long)(0xFFFFFFFFu - (uint32_t)i);
    atomicMax(&g_best, pk);
}

__global__ void k_out(float* out) {
    unsigned long long bst = g_best;
    uint32_t i = 0xFFFFFFFFu - (uint32_t)(bst & 0xFFFFFFFFull);
    if (i >= V_DIM) i = 0;
    out[0] = (float)g_order[i];
}

// ---------------- launch ----------------
extern "C" void kernel_launch(void* const* d_in, const int* in_sizes, int n_in,
                              void* d_out, int out_size) {
    const float* batch = (const float*)d_in[0];
    const float* pw    = (const float*)d_in[1];
    const float* W     = (const float*)d_in[2];
    const float* bias  = (const float*)d_in[3];

    void* hist_ptr = nullptr;
    void* fill_ptr = nullptr;
    cudaGetSymbolAddress(&hist_ptr, g_hist);
    cudaGetSymbolAddress(&fill_ptr, g_fill);

    k_reset<<<1, 32>>>();                    // idx 0
    k_scoredot<<<S_LEN, 256>>>(batch, pw);   // idx 1
    k_softmax_scores<<<1, 1024>>>();         // idx 2
    k_pool_part<<<dim3(4, POOL_CH), 128>>>(batch);  // idx 3
    k_pool_reduce<<<8, 256>>>();             // idx 4
    k_logits_part<<<dim3(125, NSEG), 128>>>(W);  // idx 5  <- profiled
    k_logits_final<<<250, 256>>>(bias);
    k_maxl<<<1, 1024>>>();
    k_exp<<<250, 256>>>();
    k_zred<<<1, 256>>>();
    cudaMemsetAsync(hist_ptr, 0, NBINS * sizeof(unsigned));
    cudaMemsetAsync(fill_ptr, 0, NBINS * sizeof(unsigned));
    k_phist<<<250, 256>>>();
    k_scanA<<<NGROUPS, 1024>>>();
    k_scanB<<<1, 1024>>>();
    k_scatter<<<250, 256>>>();
    k_rank<<<1024, 256>>>();
    k_cummask<<<1, 1024>>>();
    k_argmax<<<250, 256>>>();
    k_out<<<1, 1>>>((float*)d_out);
}

// round 15
// speedup vs baseline: 1.0344x; 1.0344x over previous
#include <cuda_runtime.h>
#include <cstdint>
#include <cstddef>

#define S_LEN 4096
#define D_DIM 2048
#define V_DIM 64000
#define NBINS (1 << 20)     // bin = key >> 12
#define NGROUPS 1024        // 1024 bins per group
#define BIN_SMEM 2048
#define NSEG 16             // split-K segments for the big GEMV
#define POOL_CH 128         // j-chunks for pooling (32 each)

// ---------------- static scratch (no allocations allowed) ----------------
__device__ float  g_s[S_LEN];
__device__ float  g_scores[S_LEN];
__device__ double g_poolacc[D_DIM];        // fp64 atomic pooled accumulator
__device__ double g_logit_part[NSEG][V_DIM];
__device__ float  g_logits[V_DIM];
__device__ unsigned g_maxi;                // order-monotone encoded max logit
__device__ float  g_e[V_DIM];
__device__ double g_zpart[256];
__device__ float  g_Z;
__device__ unsigned g_key[V_DIM];
__device__ unsigned g_hist[NBINS];
__device__ unsigned g_base[NBINS];
__device__ unsigned g_fill[NBINS];
__device__ unsigned g_groupsum[NGROUPS];
__device__ unsigned g_groupbase[NGROUPS];
__device__ int      g_nbins;
__device__ int      g_binlist[NBINS];
__device__ unsigned g_slotkey[V_DIM];
__device__ int      g_slotidx[V_DIM];
__device__ float    g_sortp[V_DIM];
__device__ int      g_order[V_DIM];
__device__ unsigned char g_mask[V_DIM];
__device__ unsigned long long g_best;

// ---------------- threefry2x32 (bit-exact JAX PRNG) ----------------
__device__ __forceinline__ uint32_t rotl32(uint32_t v, int n) {
    return (v << n) | (v >> (32 - n));
}

__device__ __forceinline__ void threefry2x32(uint32_t k0, uint32_t k1,
                                             uint32_t& x0, uint32_t& x1) {
    uint32_t ks[3] = {k0, k1, k0 ^ k1 ^ 0x1BD11BDAu};
    const int rotA[4] = {13, 15, 26, 6};
    const int rotB[4] = {17, 29, 16, 24};
    x0 += ks[0]; x1 += ks[1];
#pragma unroll
    for (int i = 0; i < 5; i++) {
        const int* r = (i & 1) ? rotB : rotA;
#pragma unroll
        for (int k = 0; k < 4; k++) {
            x0 += x1;
            x1 = rotl32(x1, r[k]);
            x1 ^= x0;
        }
        x0 += ks[(i + 1) % 3];
        x1 += ks[(i + 2) % 3] + (uint32_t)(i + 1);
    }
}

// ---------------- kernels ----------------
// kernel 0: s[j] = batch[j,:] . pool_w  (also resets tiny per-replay state)
__global__ void k_scoredot(const float* __restrict__ batch,
                           const float* __restrict__ pw) {
    int j = blockIdx.x;
    int t = threadIdx.x;  // 256
    if (j == 0 && t == 0) { g_best = 0ull; g_nbins = 0; g_maxi = 0u; }
    const float4* row4 = reinterpret_cast<const float4*>(batch + (size_t)j * D_DIM);
    const float4* pw4  = reinterpret_cast<const float4*>(pw);
    double acc = 0.0;
#pragma unroll
    for (int k = 0; k < 2; k++) {
        int i = t + k * 256;          // 512 float4 = 2048 floats
        float4 a = row4[i];
        float4 b = pw4[i];
        acc += (double)(a.x * b.x);
        acc += (double)(a.y * b.y);
        acc += (double)(a.z * b.z);
        acc += (double)(a.w * b.w);
    }
    __shared__ double sm[256];
    sm[t] = acc;
    __syncthreads();
    for (int o = 128; o > 0; o >>= 1) {
        if (t < o) sm[t] += sm[t + o];
        __syncthreads();
    }
    if (t == 0) g_s[j] = (float)sm[0];
}

// kernel 1: softmax over S (single block)
__global__ void k_softmax_scores() {
    __shared__ float smx[1024];
    __shared__ double smd[1024];
    int t = threadIdx.x;
    float m = -3.4e38f;
    for (int i = t; i < S_LEN; i += 1024) m = fmaxf(m, g_s[i]);
    smx[t] = m;
    __syncthreads();
    for (int o = 512; o > 0; o >>= 1) {
        if (t < o) smx[t] = fmaxf(smx[t], smx[t + o]);
        __syncthreads();
    }
    float gm = smx[0];
    __syncthreads();
    double sum = 0.0;
    for (int i = t; i < S_LEN; i += 1024) {
        float e = expf(g_s[i] - gm);
        g_scores[i] = e;
        sum += (double)e;
    }
    smd[t] = sum;
    __syncthreads();
    for (int o = 512; o > 0; o >>= 1) {
        if (t < o) smd[t] += smd[t + o];
        __syncthreads();
    }
    float Z = (float)smd[0];
    __syncthreads();
    for (int i = t; i < S_LEN; i += 1024) g_scores[i] = g_scores[i] / Z;
}

// kernel 2: pooled (fused): float4 across d, fp32 chunk-of-8, fp64 atomic fold
// (atomic order perturbs fp64 sum by ~1e-16 rel — negligible vs 3.8e-7 gaps)
__global__ void k_pool(const float* __restrict__ batch) {
    int d4 = blockIdx.x * 128 + threadIdx.x;  // grid.x = 4 -> 512 float4 lanes
    int c = blockIdx.y;                        // 0..127
    int j0 = c * 32;
    const float4* b4 = reinterpret_cast<const float4*>(batch);
    double a0 = 0.0, a1 = 0.0, a2 = 0.0, a3 = 0.0;
#pragma unroll
    for (int jj = 0; jj < 32; jj += 8) {
        float c0 = 0.f, c1 = 0.f, c2 = 0.f, c3 = 0.f;
#pragma unroll
        for (int k = 0; k < 8; k++) {
            int j = j0 + jj + k;
            float s = g_scores[j];
            float4 b = b4[(size_t)j * (D_DIM / 4) + d4];
            c0 = fmaf(s, b.x, c0);
            c1 = fmaf(s, b.y, c1);
            c2 = fmaf(s, b.z, c2);
            c3 = fmaf(s, b.w, c3);
        }
        a0 += (double)c0;
        a1 += (double)c1;
        a2 += (double)c2;
        a3 += (double)c3;
    }
    int d = d4 * 4;
    atomicAdd(&g_poolacc[d + 0], a0);
    atomicAdd(&g_poolacc[d + 1], a1);
    atomicAdd(&g_poolacc[d + 2], a2);
    atomicAdd(&g_poolacc[d + 3], a3);
}

// kernel 3 (PROFILED): big GEMV, float4 across v; chunk-of-16, 4 chains, fp64 fold
__global__ void __launch_bounds__(128) k_logits_part(const float* __restrict__ W) {
    int v4 = blockIdx.x * 128 + threadIdx.x;  // grid.x = 125 -> 16000 float4 lanes
    int seg = blockIdx.y;                      // 0..15
    int d0 = seg * 128;
    __shared__ float sp[128];
    if (threadIdx.x < 128) sp[threadIdx.x] = (float)g_poolacc[d0 + threadIdx.x];
    __syncthreads();
    const float4* wp = reinterpret_cast<const float4*>(W) + (size_t)d0 * (V_DIM / 4) + v4;
    double ax = 0.0, ay = 0.0, az = 0.0, aw = 0.0;
    for (int d = 0; d < 128; d += 16) {
        float4 w[16];
#pragma unroll
        for (int k = 0; k < 16; k++)
            w[k] = wp[(size_t)(d + k) * (V_DIM / 4)];
        float x0 = 0.f, x1 = 0.f, x2 = 0.f, x3 = 0.f;
        float y0 = 0.f, y1 = 0.f, y2 = 0.f, y3 = 0.f;
        float z0 = 0.f, z1 = 0.f, z2 = 0.f, z3 = 0.f;
        float u0 = 0.f, u1 = 0.f, u2 = 0.f, u3 = 0.f;
#pragma unroll
        for (int k = 0; k < 16; k += 4) {
            float p0 = sp[d + k + 0], p1 = sp[d + k + 1];
            float p2 = sp[d + k + 2], p3 = sp[d + k + 3];
            x0 = fmaf(p0, w[k + 0].x, x0); x1 = fmaf(p1, w[k + 1].x, x1);
            x2 = fmaf(p2, w[k + 2].x, x2); x3 = fmaf(p3, w[k + 3].x, x3);
            y0 = fmaf(p0, w[k + 0].y, y0); y1 = fmaf(p1, w[k + 1].y, y1);
            y2 = fmaf(p2, w[k + 2].y, y2); y3 = fmaf(p3, w[k + 3].y, y3);
            z0 = fmaf(p0, w[k + 0].z, z0); z1 = fmaf(p1, w[k + 1].z, z1);
            z2 = fmaf(p2, w[k + 2].z, z2); z3 = fmaf(p3, w[k + 3].z, z3);
            u0 = fmaf(p0, w[k + 0].w, u0); u1 = fmaf(p1, w[k + 1].w, u1);
            u2 = fmaf(p2, w[k + 2].w, u2); u3 = fmaf(p3, w[k + 3].w, u3);
        }
        ax += (double)((x0 + x1) + (x2 + x3));
        ay += (double)((y0 + y1) + (y2 + y3));
        az += (double)((z0 + z1) + (z2 + z3));
        aw += (double)((u0 + u1) + (u2 + u3));
    }
    int v = v4 * 4;
    g_logit_part[seg][v + 0] = ax;
    g_logit_part[seg][v + 1] = ay;
    g_logit_part[seg][v + 2] = az;
    g_logit_part[seg][v + 3] = aw;
}

// kernel 4: combine + bias + temperature; fold global max via monotone atomicMax
__global__ void k_logits_final(const float* __restrict__ b) {
    int v = blockIdx.x * 256 + threadIdx.x;  // grid 250
    double s = 0.0;
#pragma unroll
    for (int k = 0; k < NSEG; k++) s += g_logit_part[k][v];
    float m = (float)s;
    m = m + b[v];
    float lg = 0.7f * m;  // TEMPERATURE
    g_logits[v] = lg;
    // order-monotone encode for atomicMax (exact max, no rounding)
    uint32_t ob = __float_as_uint(lg);
    ob = (ob & 0x80000000u) ? ~ob : (ob | 0x80000000u);
    __shared__ unsigned sm[256];
    sm[threadIdx.x] = ob;
    __syncthreads();
    for (int o = 128; o > 0; o >>= 1) {
        if (threadIdx.x < o) sm[threadIdx.x] = max(sm[threadIdx.x], sm[threadIdx.x + o]);
        __syncthreads();
    }
    if (threadIdx.x == 0) atomicMax(&g_maxi, sm[0]);
}

// kernel 5: exp + Z partials
__global__ void k_exp() {
    unsigned enc = g_maxi;
    float maxl = (enc & 0x80000000u) ? __uint_as_float(enc & 0x7FFFFFFFu)
                                     : __uint_as_float(~enc);
    int v = blockIdx.x * 256 + threadIdx.x;
    float e = expf(g_logits[v] - maxl);
    g_e[v] = e;
    __shared__ double sd[256];
    sd[threadIdx.x] = (double)e;
    __syncthreads();
    for (int o = 128; o > 0; o >>= 1) {
        if (threadIdx.x < o) sd[threadIdx.x] += sd[threadIdx.x + o];
        __syncthreads();
    }
    if (threadIdx.x == 0) g_zpart[blockIdx.x] = sd[0];
}

__global__ void k_zred() {
    __shared__ double sd[256];
    int t = threadIdx.x;
    sd[t] = (t < 250) ? g_zpart[t] : 0.0;
    __syncthreads();
    for (int o = 128; o > 0; o >>= 1) {
        if (t < o) sd[t] += sd[t + o];
        __syncthreads();
    }
    if (t == 0) g_Z = (float)sd[0];
}

__global__ void k_phist() {
    int v = blockIdx.x * 256 + threadIdx.x;
    float p = g_e[v] / g_Z;
    unsigned key = __float_as_uint(p);
    g_key[v] = key;
    atomicAdd(&g_hist[key >> 12], 1u);
}

__global__ void k_scanA() {
    int g = blockIdx.x;       // 0..1023
    int t = threadIdx.x;      // 1024
    int b = g * 1024 + t;
    unsigned h = g_hist[b];
    __shared__ unsigned s[1024];
    s[t] = h;
    __syncthreads();
    for (int off = 1; off < 1024; off <<= 1) {
        unsigned add = (t >= off) ? s[t - off] : 0u;
        __syncthreads();
        s[t] += add;
        __syncthreads();
    }
    unsigned total = s[1023];
    g_base[b] = total - s[t];
    if (t == 0) g_groupsum[g] = total;
    if (h > 0) {
        int p = atomicAdd(&g_nbins, 1);
        g_binlist[p] = b;
    }
}

__global__ void k_scanB() {
    int t = threadIdx.x;  // 1024
    __shared__ unsigned s[1024];
    s[t] = g_groupsum[t];
    __syncthreads();
    for (int off = 1; off < 1024; off <<= 1) {
        unsigned add = (t >= off) ? s[t - off] : 0u;
        __syncthreads();
        s[t] += add;
        __syncthreads();
    }
    unsigned total = s[1023];
    g_groupbase[t] = total - s[t];
}

__global__ void k_scatter() {
    int v = blockIdx.x * 256 + threadIdx.x;
    unsigned key = g_key[v];
    unsigned b = key >> 12;
    unsigned pos = g_groupbase[b >> 10] + g_base[b] + atomicAdd(&g_fill[b], 1u);
    g_slotkey[pos] = key;
    g_slotidx[pos] = v;
}

__global__ void k_rank() {
    __shared__ unsigned sk[BIN_SMEM];
    __shared__ int si[BIN_SMEM];
    int nb = g_nbins;
    for (int bi = blockIdx.x; bi < nb; bi += gridDim.x) {
        int b = g_binlist[bi];
        unsigned c = g_hist[b];
        unsigned base = g_groupbase[b >> 10] + g_base[b];
        if (c <= BIN_SMEM) {
            for (unsigned e = threadIdx.x; e < c; e += blockDim.x) {
                sk[e] = g_slotkey[base + e];
                si[e] = g_slotidx[base + e];
            }
            __syncthreads();
            for (unsigned e = threadIdx.x; e < c; e += blockDim.x) {
                unsigned ke = sk[e];
                int ide = si[e];
                unsigned r = 0;
                for (unsigned u = 0; u < c; u++) {
                    unsigned ku = sk[u];
                    r += (ku > ke) || (ku == ke && si[u] < ide);
                }
                g_sortp[base + r] = __uint_as_float(ke);
                g_order[base + r] = ide;
            }
            __syncthreads();
        } else {
            for (unsigned e = threadIdx.x; e < c; e += blockDim.x) {
                unsigned ke = g_slotkey[base + e];
                int ide = g_slotidx[base + e];
                unsigned r = 0;
                for (unsigned u = 0; u < c; u++) {
                    unsigned ku = g_slotkey[base + u];
                    r += (ku > ke) || (ku == ke && g_slotidx[base + u] < ide);
                }
                g_sortp[base + r] = __uint_as_float(ke);
                g_order[base + r] = ide;
            }
            __syncthreads();
        }
    }
}

__global__ void k_cummask() {
    __shared__ double sd[1024];
    int t = threadIdx.x;
    int i0 = t * 64;
    double s = 0.0;
    for (int k = 0; k < 64; k++) {
        int i = i0 + k;
        if (i < V_DIM) s += (double)g_sortp[i];
    }
    sd[t] = s;
    __syncthreads();
    for (int off = 1; off < 1024; off <<= 1) {
        double add = (t >= off) ? sd[t - off] : 0.0;
        __syncthreads();
        sd[t] += add;
        __syncthreads();
    }
    double run = (t > 0) ? sd[t - 1] : 0.0;
    for (int k = 0; k < 64; k++) {
        int i = i0 + k;
        if (i < V_DIM) {
            run += (double)g_sortp[i];
            g_mask[i] = (run <= 0.5) ? 1 : 0;
        }
    }
}

// gumbel-argmax; JAX partitionable threefry, 32-bit draw = y0 ^ y1
__global__ void k_argmax() {
    int i = blockIdx.x * 256 + threadIdx.x;
    if (i >= V_DIM) return;
    if (!g_mask[i]) return;
    uint32_t x0 = 0u, x1 = (uint32_t)i;
    threefry2x32(0u, 42u, x0, x1);
    uint32_t bits = x0 ^ x1;
    float f = __uint_as_float((bits >> 9) | 0x3f800000u) - 1.0f;  // [0,1)
    float u = (f > 0.0f) ? f : 1.17549435e-38f;
    float g = -logf(-logf(u));
    float val = logf(g_sortp[i]) + g;
    uint32_t ob = __float_as_uint(val);
    ob = (ob & 0x80000000u) ? ~ob : (ob | 0x80000000u);
    unsigned long long pk =
        (((unsigned long long)ob) << 32) |
        (unsigned long long)(0xFFFFFFFFu - (uint32_t)i);
    atomicMax(&g_best, pk);
}

__global__ void k_out(float* out) {
    unsigned long long bst = g_best;
    uint32_t i = 0xFFFFFFFFu - (uint32_t)(bst & 0xFFFFFFFFull);
    if (i >= V_DIM) i = 0;
    out[0] = (float)g_order[i];
}

// ---------------- launch ----------------
extern "C" void kernel_launch(void* const* d_in, const int* in_sizes, int n_in,
                              void* d_out, int out_size) {
    const float* batch = (const float*)d_in[0];
    const float* pw    = (const float*)d_in[1];
    const float* W     = (const float*)d_in[2];
    const float* bias  = (const float*)d_in[3];

    void* hist_ptr = nullptr;
    void* fill_ptr = nullptr;
    void* pool_ptr = nullptr;
    cudaGetSymbolAddress(&hist_ptr, g_hist);
    cudaGetSymbolAddress(&fill_ptr, g_fill);
    cudaGetSymbolAddress(&pool_ptr, g_poolacc);
    cudaMemsetAsync(pool_ptr, 0, D_DIM * sizeof(double));
    cudaMemsetAsync(hist_ptr, 0, NBINS * sizeof(unsigned));
    cudaMemsetAsync(fill_ptr, 0, NBINS * sizeof(unsigned));

    k_scoredot<<<S_LEN, 256>>>(batch, pw);        // kernel 0 (resets scalars)
    k_softmax_scores<<<1, 1024>>>();              // kernel 1
    k_pool<<<dim3(4, POOL_CH), 128>>>(batch);     // kernel 2
    k_logits_part<<<dim3(125, NSEG), 128>>>(W);   // kernel 3  <- PROFILED
    k_logits_final<<<250, 256>>>(bias);           // kernel 4 (+max fold)
    k_exp<<<250, 256>>>();                        // kernel 5
    k_zred<<<1, 256>>>();
    k_phist<<<250, 256>>>();
    k_scanA<<<NGROUPS, 1024>>>();
    k_scanB<<<1, 1024>>>();
    k_scatter<<<250, 256>>>();
    k_rank<<<1024, 256>>>();
    k_cummask<<<1, 1024>>>();
    k_argmax<<<250, 256>>>();
    k_out<<<1, 1>>>((float*)d_out);
}